// round 7
// baseline (speedup 1.0000x reference)
#include <cuda_runtime.h>
#include <cstdint>
#include <math.h>

// Problem constants (fixed by the dataset)
#define BB 2
#define SS 2048
#define DD 512
#define HH 8
#define DH 64
#define BH (BB*HH)          // 16
#define MAXK 32
#define EPSF 1e-8f

// ---------------- scratch (static device globals; no allocs allowed) --------
__device__ float g_q  [BB*HH*SS*DH];   // [B,H,S,64]
__device__ float g_kT [BB*HH*DH*SS];   // [B,H,64,S]
__device__ float g_v  [BB*HH*SS*DH];   // [B,H,S,64]
__device__ float g_attn[BB*SS*DD];     // [B,S,D]

// ---------------- warp reduce helpers ---------------------------------------
__device__ __forceinline__ float warpMaxF(float v){
#pragma unroll
    for (int o = 16; o; o >>= 1) v = fmaxf(v, __shfl_xor_sync(0xffffffffu, v, o));
    return v;
}
__device__ __forceinline__ float warpSumF(float v){
#pragma unroll
    for (int o = 16; o; o >>= 1) v += __shfl_xor_sync(0xffffffffu, v, o);
    return v;
}
__device__ __forceinline__ unsigned warpMaxU(unsigned v){
#pragma unroll
    for (int o = 16; o; o >>= 1) { unsigned t = __shfl_xor_sync(0xffffffffu, v, o); v = t > v ? t : v; }
    return v;
}
__device__ __forceinline__ int warpSumI(int v){
#pragma unroll
    for (int o = 16; o; o >>= 1) v += __shfl_xor_sync(0xffffffffu, v, o);
    return v;
}
// monotone float -> uint mapping (descending float order == descending uint order)
__device__ __forceinline__ unsigned ordf(float f){
    unsigned u = __float_as_uint(f);
    return (u & 0x80000000u) ? ~u : (u | 0x80000000u);
}

// ---------------- SGEMM: C[M,N] = A[M,K] * Bw[N,K]^T + bias ------------------
// Double-buffered smem pipeline (R3 version: measured 186/45us, DRAM ~0).
// MODE 0: plain store. MODE 1: q/kT/v scatter.
template<int MODE>
__global__ __launch_bounds__(256, 2)
void sgemm_nt(const float* __restrict__ A, const float* __restrict__ Bw,
              const float* __restrict__ bias, float* __restrict__ C,
              int M, int N, int K)
{
    const int BM = 128, BN = 128, BK = 16;
    __shared__ float As[2][BK][BM + 4];
    __shared__ float Bs[2][BK][BN + 4];

    int tid = threadIdx.x;
    int tx = tid & 15, ty = tid >> 4;
    int bm = blockIdx.y * BM, bn = blockIdx.x * BN;

    int lrow0 = tid >> 2,            lc0 = (tid & 3) * 4;
    int lrow1 = (tid + 256) >> 2,    lc1 = lc0;

    float acc[8][8];
#pragma unroll
    for (int i = 0; i < 8; i++)
#pragma unroll
        for (int j = 0; j < 8; j++) acc[i][j] = 0.f;

    const float* Ab = A + (size_t)bm * K;
    const float* Bb = Bw + (size_t)bn * K;

    float4 pa0, pa1, pb0, pb1;

    pa0 = *(const float4*)(Ab + (size_t)lrow0 * K + lc0);
    pa1 = *(const float4*)(Ab + (size_t)lrow1 * K + lc1);
    pb0 = *(const float4*)(Bb + (size_t)lrow0 * K + lc0);
    pb1 = *(const float4*)(Bb + (size_t)lrow1 * K + lc1);
    As[0][lc0+0][lrow0]=pa0.x; As[0][lc0+1][lrow0]=pa0.y; As[0][lc0+2][lrow0]=pa0.z; As[0][lc0+3][lrow0]=pa0.w;
    As[0][lc1+0][lrow1]=pa1.x; As[0][lc1+1][lrow1]=pa1.y; As[0][lc1+2][lrow1]=pa1.z; As[0][lc1+3][lrow1]=pa1.w;
    Bs[0][lc0+0][lrow0]=pb0.x; Bs[0][lc0+1][lrow0]=pb0.y; Bs[0][lc0+2][lrow0]=pb0.z; Bs[0][lc0+3][lrow0]=pb0.w;
    Bs[0][lc1+0][lrow1]=pb1.x; Bs[0][lc1+1][lrow1]=pb1.y; Bs[0][lc1+2][lrow1]=pb1.z; Bs[0][lc1+3][lrow1]=pb1.w;
    __syncthreads();

    for (int k0 = 0; k0 < K; k0 += BK) {
        int buf = (k0 >> 4) & 1;
        bool more = (k0 + BK) < K;
        if (more) {
            int kn = k0 + BK;
            pa0 = *(const float4*)(Ab + (size_t)lrow0 * K + kn + lc0);
            pa1 = *(const float4*)(Ab + (size_t)lrow1 * K + kn + lc1);
            pb0 = *(const float4*)(Bb + (size_t)lrow0 * K + kn + lc0);
            pb1 = *(const float4*)(Bb + (size_t)lrow1 * K + kn + lc1);
        }
#pragma unroll
        for (int k = 0; k < BK; k++) {
            float4 a0 = *(const float4*)&As[buf][k][ty * 8];
            float4 a1 = *(const float4*)&As[buf][k][ty * 8 + 4];
            float4 b0 = *(const float4*)&Bs[buf][k][tx * 8];
            float4 b1 = *(const float4*)&Bs[buf][k][tx * 8 + 4];
            float av[8] = {a0.x,a0.y,a0.z,a0.w,a1.x,a1.y,a1.z,a1.w};
            float bv[8] = {b0.x,b0.y,b0.z,b0.w,b1.x,b1.y,b1.z,b1.w};
#pragma unroll
            for (int i = 0; i < 8; i++)
#pragma unroll
                for (int j = 0; j < 8; j++) acc[i][j] = fmaf(av[i], bv[j], acc[i][j]);
        }
        if (more) {
            int nb = buf ^ 1;
            As[nb][lc0+0][lrow0]=pa0.x; As[nb][lc0+1][lrow0]=pa0.y; As[nb][lc0+2][lrow0]=pa0.z; As[nb][lc0+3][lrow0]=pa0.w;
            As[nb][lc1+0][lrow1]=pa1.x; As[nb][lc1+1][lrow1]=pa1.y; As[nb][lc1+2][lrow1]=pa1.z; As[nb][lc1+3][lrow1]=pa1.w;
            Bs[nb][lc0+0][lrow0]=pb0.x; Bs[nb][lc0+1][lrow0]=pb0.y; Bs[nb][lc0+2][lrow0]=pb0.z; Bs[nb][lc0+3][lrow0]=pb0.w;
            Bs[nb][lc1+0][lrow1]=pb1.x; Bs[nb][lc1+1][lrow1]=pb1.y; Bs[nb][lc1+2][lrow1]=pb1.z; Bs[nb][lc1+3][lrow1]=pb1.w;
        }
        __syncthreads();
    }

    if (MODE == 0) {
#pragma unroll
        for (int i = 0; i < 8; i++) {
            int mrow = bm + ty * 8 + i;
#pragma unroll
            for (int g = 0; g < 2; g++) {
                int col = bn + tx * 8 + g * 4;
                float4 bv = *(const float4*)(bias + col);
                float4 o;
                o.x = acc[i][g*4+0] + bv.x; o.y = acc[i][g*4+1] + bv.y;
                o.z = acc[i][g*4+2] + bv.z; o.w = acc[i][g*4+3] + bv.w;
                *(float4*)(C + (size_t)mrow * N + col) = o;
            }
        }
    } else {
#pragma unroll
        for (int i = 0; i < 8; i++) {
            int mrow = bm + ty * 8 + i;
            int b = mrow >> 11;          // S = 2048
            int s = mrow & 2047;
#pragma unroll
            for (int j = 0; j < 8; j++) {
                int n = bn + tx * 8 + j;
                float val = acc[i][j] + bias[n];
                int sec = n >> 9;        // 0:q 1:k 2:v (D = 512)
                int nn  = n & 511;
                int head = nn >> 6, d = nn & 63;
                if (sec == 0)
                    g_q [((size_t)((b*HH+head)*SS) + s)*DH + d] = val;
                else if (sec == 1)
                    g_kT[((size_t)((b*HH+head)*DH) + d)*SS + s] = val;
                else
                    g_v [((size_t)((b*HH+head)*SS) + s)*DH + d] = val;
            }
        }
    }
}

// ---------------- fused attention v4 -----------------------------------------
// TQ=32 queries/block, 512 threads (16 warps). Columns processed in 2 chunks of
// 1024; warp w covers 64 cols per chunk (lane owns 2). Per-row online stats
// (max, Z, S1 = sum p*(s-m), argmax tie count+index) held lane-owned (row=lane)
// and merged across chunks with exact shift identities. Cross-warp combine via
// smem [32][16]; warp w finalizes rows w and w+16. H = logZ - S1/Z.
// Fast path (H>=1.2 & unique argmax): out = V[argmax]/(1+EPS*Z).
// Exact deterministic fallback recomputes the row and runs reference-semantics
// entropy/top-k (cold; never taken for this data distribution).
#define TQ 32
#define ATHREADS 512

__global__ __launch_bounds__(ATHREADS, 1)
void attn_kernel()
{
    __shared__ float s_qT[DH * TQ];          // [d][i]  8KB
    __shared__ float s_m [TQ][16];
    __shared__ float s_z [TQ][16];
    __shared__ float s_s1[TQ][16];
    __shared__ int   s_ct[TQ][16];
    __shared__ int   s_j0[TQ][16];

    int bh = blockIdx.y;
    int q0 = blockIdx.x * TQ;
    const float* Q  = g_q  + ((size_t)bh * SS + q0) * DH;
    const float* KT = g_kT + (size_t)bh * DH * SS;
    const float* V  = g_v  + (size_t)bh * SS * DH;
    int tid = threadIdx.x, lane = tid & 31, w = tid >> 5;

    for (int e = tid; e < TQ * DH; e += ATHREADS) {
        int i = e & 31, d = e >> 5;
        s_qT[d * TQ + i] = Q[i * DH + d];
    }
    __syncthreads();

    const float scale = 0.125f;   // 1/sqrt(64)

    // lane-owned running stats for row == lane
    float rm = 0.f, rz = 0.f, rs1 = 0.f;
    int rcnt = 0, rj0 = 0;

#pragma unroll
    for (int ch = 0; ch < 2; ch++) {
        int c0 = ch * 1024 + w * 64 + lane * 2;
        float acc[TQ][2];
#pragma unroll
        for (int i = 0; i < TQ; i++) { acc[i][0] = 0.f; acc[i][1] = 0.f; }

#pragma unroll 4
        for (int d = 0; d < DH; d++) {
            float2 k2 = *(const float2*)(KT + (size_t)d * SS + c0);
            const float4* qp = (const float4*)(s_qT + d * TQ);   // broadcast
#pragma unroll
            for (int g = 0; g < 8; g++) {
                float4 q4 = qp[g];
                acc[g*4+0][0] = fmaf(q4.x, k2.x, acc[g*4+0][0]);
                acc[g*4+0][1] = fmaf(q4.x, k2.y, acc[g*4+0][1]);
                acc[g*4+1][0] = fmaf(q4.y, k2.x, acc[g*4+1][0]);
                acc[g*4+1][1] = fmaf(q4.y, k2.y, acc[g*4+1][1]);
                acc[g*4+2][0] = fmaf(q4.z, k2.x, acc[g*4+2][0]);
                acc[g*4+2][1] = fmaf(q4.z, k2.y, acc[g*4+2][1]);
                acc[g*4+3][0] = fmaf(q4.w, k2.x, acc[g*4+3][0]);
                acc[g*4+3][1] = fmaf(q4.w, k2.y, acc[g*4+3][1]);
            }
        }

        // per-row warp stats for this chunk; lane i keeps row i
#pragma unroll
        for (int i = 0; i < TQ; i++) {
            float v0 = acc[i][0] * scale, v1 = acc[i][1] * scale;
            float ml = warpMaxF(fmaxf(v0, v1));
            float e0 = expf(v0 - ml), e1 = expf(v1 - ml);
            float zl  = warpSumF(e0 + e1);
            float s1l = warpSumF(fmaf(e0, v0 - ml, e1 * (v1 - ml)));
            int lc = (v0 == ml) + (v1 == ml);
            int li = (v0 == ml) ? c0 : c0 + 1;
            int ct = warpSumI(lc);
            unsigned msk = __ballot_sync(0xffffffffu, lc > 0);
            int src = __ffs((int)msk) - 1;
            int j0c = __shfl_sync(0xffffffffu, li, src);
            if (lane == i) {
                if (ch == 0) {
                    rm = ml; rz = zl; rs1 = s1l; rcnt = ct; rj0 = j0c;
                } else {
                    float newm = fmaxf(rm, ml);
                    float d1 = rm - newm, d2 = ml - newm;
                    float f1 = expf(d1), f2 = expf(d2);
                    rs1 = f1 * fmaf(d1, rz, rs1) + f2 * fmaf(d2, zl, s1l);
                    rz  = f1 * rz + f2 * zl;
                    if (ml > rm)       { rcnt = ct; rj0 = j0c; }
                    else if (ml == rm) { rcnt += ct; }
                    rm = newm;
                }
            }
        }
    }

    // publish lane-owned row stats: s_*[row=lane][warp=w]
    s_m [lane][w] = rm;  s_z [lane][w] = rz;  s_s1[lane][w] = rs1;
    s_ct[lane][w] = rcnt; s_j0[lane][w] = rj0;
    __syncthreads();

    int b = bh >> 3, hd = bh & 7;

    // warp w finalizes rows w and w+16
#pragma unroll
    for (int rr0 = 0; rr0 < 2; rr0++) {
        int rr = w + rr0 * 16;
        bool act = lane < 16;
        float mlv = act ? s_m[rr][lane] : -3.0e38f;
        float m = warpMaxF(mlv);
        float zlv = act ? s_z[rr][lane] : 0.f;
        float r = act ? expf(mlv - m) : 0.f;
        float z  = warpSumF(r * zlv);
        float s1 = warpSumF(act ? r * fmaf(mlv - m, zlv, s_s1[rr][lane]) : 0.f);
        float hent = logf(z) - s1 / z;
        int ctv = (act && mlv == m) ? s_ct[rr][lane] : 0;
        int cnt = warpSumI(ctv);
        unsigned msk = __ballot_sync(0xffffffffu, ctv > 0);
        int src = __ffs((int)msk) - 1;
        int jv = act ? s_j0[rr][lane] : 0;
        int j0 = __shfl_sync(0xffffffffu, jv, src);

        float* outp = &g_attn[((size_t)(b * SS + q0 + rr)) * DD + hd * DH + lane * 2];

        if (hent >= 1.2f && cnt == 1) {
            // tk = 1 guaranteed (32*(1-H) < 1), unique argmax: p = 1, P = 1.
            float wgt = 1.0f / (1.0f + EPSF * z);
            float2 vv = *(const float2*)(V + (size_t)j0 * DH + lane * 2);
            float2 o; o.x = vv.x * wgt; o.y = vv.y * wgt;
            *(float2*)outp = o;
        } else {
            // ---- exact deterministic fallback (cold) -----------------------
            float fb[64];
            for (int jj = 0; jj < 64; jj++) {
                int j = lane + (jj << 5);
                float s = 0.f;
                for (int d = 0; d < DH; d++)
                    s = fmaf(s_qT[d * TQ + rr], KT[(size_t)d * SS + j], s);
                fb[jj] = s * scale;
            }
            float m2 = -3.0e38f;
            for (int jj = 0; jj < 64; jj++) m2 = fmaxf(m2, fb[jj]);
            m2 = warpMaxF(m2);
            float z2 = 0.f;
            for (int jj = 0; jj < 64; jj++) z2 += expf(fb[jj] - m2);
            z2 = warpSumF(z2);
            float invZ = 1.0f / z2;
            float he = 0.f;
            for (int jj = 0; jj < 64; jj++) {
                float p  = expf(fb[jj] - m2);
                float ww = p * invZ;
                he -= ww * logf(ww + EPSF);
            }
            he = warpSumF(he);
            int tk = (int)(32.0f * (1.0f - he));
            tk = tk < 1 ? 1 : (tk > MAXK ? MAXK : tk);

            unsigned thr_u;
            if (tk == 1) {
                thr_u = ordf(m2);
            } else {
                thr_u = 0xFFFFFFFFu;
                int removed = 0;
                while (removed < tk) {
                    unsigned best = 0u;
                    for (int jj = 0; jj < 64; jj++) {
                        unsigned u = ordf(fb[jj]);
                        if (u < thr_u && u > best) best = u;
                    }
                    best = warpMaxU(best);
                    int c = 0;
                    for (int jj = 0; jj < 64; jj++) c += (ordf(fb[jj]) == best);
                    c = warpSumI(c);
                    removed += c;
                    thr_u = best;
                }
            }

            float P = 0.f;
            for (int jj = 0; jj < 64; jj++)
                if (ordf(fb[jj]) >= thr_u) P += expf(fb[jj] - m2);
            P = warpSumF(P);
            float invDen = 1.0f / (P + EPSF * z2);

            float r0 = 0.f, r1 = 0.f;
            for (int d0 = 0; d0 < DH; d0 += 2) {
                float a0 = 0.f, a1 = 0.f;
                for (int jj = 0; jj < 64; jj++) {
                    float s = fb[jj];
                    if (ordf(s) >= thr_u) {
                        int j = lane + (jj << 5);
                        float p = expf(s - m2);
                        float2 vv = *(const float2*)(V + (size_t)j * DH + d0);
                        a0 = fmaf(p, vv.x, a0);
                        a1 = fmaf(p, vv.y, a1);
                    }
                }
                a0 = warpSumF(a0);
                a1 = warpSumF(a1);
                if (lane == (d0 >> 1)) { r0 = a0; r1 = a1; }
            }
            float2 o; o.x = r0 * invDen; o.y = r1 * invDen;
            *(float2*)outp = o;
        }
    }
}

// ---------------- launch -----------------------------------------------------
extern "C" void kernel_launch(void* const* d_in, const int* in_sizes, int n_in,
                              void* d_out, int out_size)
{
    const float* x     = (const float*)d_in[0];
    const float* w_in  = (const float*)d_in[1];
    const float* b_in  = (const float*)d_in[2];
    const float* w_out = (const float*)d_in[3];
    const float* b_out = (const float*)d_in[4];
    float* out = (float*)d_out;

    float* pattn = nullptr;
    cudaGetSymbolAddress((void**)&pattn, g_attn);

    // 1) QKV projection with head-layout scatter
    sgemm_nt<1><<<dim3((3*DD)/128, (BB*SS)/128), 256>>>(
        x, w_in, b_in, nullptr, BB*SS, 3*DD, DD);

    // 2) fused attention + entropy top-k
    attn_kernel<<<dim3(SS/TQ, BH), ATHREADS>>>();

    // 3) output projection
    sgemm_nt<0><<<dim3(DD/128, (BB*SS)/128), 256>>>(
        pattn, w_out, b_out, out, BB*SS, DD, DD);
}

// round 8
// speedup vs baseline: 1.2456x; 1.2456x over previous
#include <cuda_runtime.h>
#include <cstdint>
#include <math.h>

// Problem constants (fixed by the dataset)
#define BB 2
#define SS 2048
#define DD 512
#define HH 8
#define DH 64
#define BH (BB*HH)          // 16
#define MAXK 32
#define EPSF 1e-8f

// ---------------- scratch (static device globals; no allocs allowed) --------
__device__ float g_q  [BB*HH*SS*DH];   // [B,H,S,64]
__device__ float g_kT [BB*HH*DH*SS];   // [B,H,64,S]
__device__ float g_v  [BB*HH*SS*DH];   // [B,H,S,64]
__device__ float g_attn[BB*SS*DD];     // [B,S,D]

// ---------------- warp reduce helpers ---------------------------------------
__device__ __forceinline__ float warpMaxF(float v){
#pragma unroll
    for (int o = 16; o; o >>= 1) v = fmaxf(v, __shfl_xor_sync(0xffffffffu, v, o));
    return v;
}
__device__ __forceinline__ float warpSumF(float v){
#pragma unroll
    for (int o = 16; o; o >>= 1) v += __shfl_xor_sync(0xffffffffu, v, o);
    return v;
}
__device__ __forceinline__ unsigned warpMaxU(unsigned v){
#pragma unroll
    for (int o = 16; o; o >>= 1) { unsigned t = __shfl_xor_sync(0xffffffffu, v, o); v = t > v ? t : v; }
    return v;
}
__device__ __forceinline__ int warpSumI(int v){
#pragma unroll
    for (int o = 16; o; o >>= 1) v += __shfl_xor_sync(0xffffffffu, v, o);
    return v;
}
// monotone float -> uint mapping (descending float order == descending uint order)
__device__ __forceinline__ unsigned ordf(float f){
    unsigned u = __float_as_uint(f);
    return (u & 0x80000000u) ? ~u : (u | 0x80000000u);
}

// ---------------- SGEMM: C[M,N] = A[M,K] * Bw[N,K]^T + bias ------------------
// BM=128 x BN=64 tiles (wave-quantization fix: 768/256 blocks vs 384/128),
// double-buffered smem, 3 CTAs/SM. MODE 0: plain store. MODE 1: qkv scatter.
template<int MODE>
__global__ __launch_bounds__(256, 3)
void sgemm_nt(const float* __restrict__ A, const float* __restrict__ Bw,
              const float* __restrict__ bias, float* __restrict__ C,
              int M, int N, int K)
{
    const int BM = 128, BN = 64, BK = 16;
    __shared__ float As[2][BK][BM + 4];
    __shared__ float Bs[2][BK][BN + 4];

    int tid = threadIdx.x;
    int tx = tid & 15, ty = tid >> 4;          // 16x16 threads: 4 cols, 8 rows each
    int bm = blockIdx.y * BM, bn = blockIdx.x * BN;

    // loaders: A = 512 float4 (2/thread), B = 256 float4 (1/thread)
    int arow0 = tid >> 2, ac = (tid & 3) * 4;
    int arow1 = arow0 + 64;
    int brow  = tid >> 2, bc = ac;

    float acc[8][4];
#pragma unroll
    for (int i = 0; i < 8; i++)
#pragma unroll
        for (int j = 0; j < 4; j++) acc[i][j] = 0.f;

    const float* Ab = A + (size_t)bm * K;
    const float* Bb = Bw + (size_t)bn * K;

    float4 pa0, pa1, pb0;

    pa0 = *(const float4*)(Ab + (size_t)arow0 * K + ac);
    pa1 = *(const float4*)(Ab + (size_t)arow1 * K + ac);
    pb0 = *(const float4*)(Bb + (size_t)brow  * K + bc);
    As[0][ac+0][arow0]=pa0.x; As[0][ac+1][arow0]=pa0.y; As[0][ac+2][arow0]=pa0.z; As[0][ac+3][arow0]=pa0.w;
    As[0][ac+0][arow1]=pa1.x; As[0][ac+1][arow1]=pa1.y; As[0][ac+2][arow1]=pa1.z; As[0][ac+3][arow1]=pa1.w;
    Bs[0][bc+0][brow ]=pb0.x; Bs[0][bc+1][brow ]=pb0.y; Bs[0][bc+2][brow ]=pb0.z; Bs[0][bc+3][brow ]=pb0.w;
    __syncthreads();

    for (int k0 = 0; k0 < K; k0 += BK) {
        int buf = (k0 >> 4) & 1;
        bool more = (k0 + BK) < K;
        if (more) {
            int kn = k0 + BK;
            pa0 = *(const float4*)(Ab + (size_t)arow0 * K + kn + ac);
            pa1 = *(const float4*)(Ab + (size_t)arow1 * K + kn + ac);
            pb0 = *(const float4*)(Bb + (size_t)brow  * K + kn + bc);
        }
#pragma unroll
        for (int k = 0; k < BK; k++) {
            float4 a0 = *(const float4*)&As[buf][k][ty * 8];
            float4 a1 = *(const float4*)&As[buf][k][ty * 8 + 4];
            float4 b0 = *(const float4*)&Bs[buf][k][tx * 4];
            float av[8] = {a0.x,a0.y,a0.z,a0.w,a1.x,a1.y,a1.z,a1.w};
            float bv[4] = {b0.x,b0.y,b0.z,b0.w};
#pragma unroll
            for (int i = 0; i < 8; i++)
#pragma unroll
                for (int j = 0; j < 4; j++) acc[i][j] = fmaf(av[i], bv[j], acc[i][j]);
        }
        if (more) {
            int nb = buf ^ 1;
            As[nb][ac+0][arow0]=pa0.x; As[nb][ac+1][arow0]=pa0.y; As[nb][ac+2][arow0]=pa0.z; As[nb][ac+3][arow0]=pa0.w;
            As[nb][ac+0][arow1]=pa1.x; As[nb][ac+1][arow1]=pa1.y; As[nb][ac+2][arow1]=pa1.z; As[nb][ac+3][arow1]=pa1.w;
            Bs[nb][bc+0][brow ]=pb0.x; Bs[nb][bc+1][brow ]=pb0.y; Bs[nb][bc+2][brow ]=pb0.z; Bs[nb][bc+3][brow ]=pb0.w;
        }
        __syncthreads();
    }

    if (MODE == 0) {
#pragma unroll
        for (int i = 0; i < 8; i++) {
            int mrow = bm + ty * 8 + i;
            int col = bn + tx * 4;
            float4 bv = *(const float4*)(bias + col);
            float4 o;
            o.x = acc[i][0] + bv.x; o.y = acc[i][1] + bv.y;
            o.z = acc[i][2] + bv.z; o.w = acc[i][3] + bv.w;
            *(float4*)(C + (size_t)mrow * N + col) = o;
        }
    } else {
#pragma unroll
        for (int i = 0; i < 8; i++) {
            int mrow = bm + ty * 8 + i;
            int b = mrow >> 11;          // S = 2048
            int s = mrow & 2047;
#pragma unroll
            for (int j = 0; j < 4; j++) {
                int n = bn + tx * 4 + j;
                float val = acc[i][j] + bias[n];
                int sec = n >> 9;        // 0:q 1:k 2:v (D = 512)
                int nn  = n & 511;
                int head = nn >> 6, d = nn & 63;
                if (sec == 0)
                    g_q [((size_t)((b*HH+head)*SS) + s)*DH + d] = val;
                else if (sec == 1)
                    g_kT[((size_t)((b*HH+head)*DH) + d)*SS + s] = val;
                else
                    g_v [((size_t)((b*HH+head)*SS) + s)*DH + d] = val;
            }
        }
    }
}

// ---------------- fused attention v2 (R3-proven) -----------------------------
// TQ=16 queries/block, 512 threads (16 warps). Phase 1: each warp computes a
// 16x128 score slab (thread tile 16x4), fused per-row max. Phase 2: warp w owns
// row w; single exp pass accumulates Z and S1=sum p*(s-m) -> entropy identity
// H = logZ - S1/Z, and records argmax ties. Fast path (H>=1.2 => tk=1): output
// = sum of tied V rows / (cnt + EPS*Z). Exact fallback otherwise (scores are
// still in smem).
#define TQ 16
#define ATHREADS 512
#define CAP 128
#define ATTN_SMEM (TQ*SS*4 + DH*TQ*4 + TQ*16*4 + TQ*4 + TQ*CAP*2)

__global__ __launch_bounds__(ATHREADS, 1)
void attn_kernel()
{
    extern __shared__ unsigned char smem[];
    float* s_sc  = (float*)smem;                              // [TQ][2048]
    float* s_qT  = s_sc + TQ * SS;                            // [64][TQ]
    float* s_max = s_qT + DH * TQ;                            // [TQ][16]
    int*   s_cnt = (int*)(s_max + TQ * 16);                   // [TQ]
    unsigned short* s_idx = (unsigned short*)(s_cnt + TQ);    // [TQ][CAP]

    int bh = blockIdx.y;
    int q0 = blockIdx.x * TQ;
    const float* Q  = g_q  + ((size_t)bh * SS + q0) * DH;
    const float* KT = g_kT + (size_t)bh * DH * SS;
    const float* V  = g_v  + (size_t)bh * SS * DH;
    int tid = threadIdx.x;
    int lane = tid & 31, w = tid >> 5;

    // load Q tile transposed: s_qT[d][i]
    for (int e = tid; e < TQ * DH; e += ATHREADS) {
        int i = e & 15, d = e >> 4;
        s_qT[d * TQ + i] = Q[i * DH + d];
    }
    __syncthreads();

    // ---- phase 1: scores. warp w covers cols [128w, 128w+128), 16 rows -----
    int c0 = w * 128 + lane * 4;
    float acc[16][4];
#pragma unroll
    for (int i = 0; i < 16; i++)
#pragma unroll
        for (int c = 0; c < 4; c++) acc[i][c] = 0.f;

#pragma unroll 4
    for (int d = 0; d < DH; d++) {
        float4 k4 = *(const float4*)(KT + (size_t)d * SS + c0);
        const float4* qp = (const float4*)(s_qT + d * TQ);
        float4 q4[4] = {qp[0], qp[1], qp[2], qp[3]};
        const float* qf = (const float*)q4;
#pragma unroll
        for (int i = 0; i < 16; i++) {
            float qi = qf[i];
            acc[i][0] = fmaf(qi, k4.x, acc[i][0]);
            acc[i][1] = fmaf(qi, k4.y, acc[i][1]);
            acc[i][2] = fmaf(qi, k4.z, acc[i][2]);
            acc[i][3] = fmaf(qi, k4.w, acc[i][3]);
        }
    }
    const float scale = 0.125f;   // 1/sqrt(64)
#pragma unroll
    for (int i = 0; i < 16; i++) {
        float4 v;
        v.x = acc[i][0]*scale; v.y = acc[i][1]*scale;
        v.z = acc[i][2]*scale; v.w = acc[i][3]*scale;
        *(float4*)&s_sc[i * SS + c0] = v;
        float rm = fmaxf(fmaxf(v.x, v.y), fmaxf(v.z, v.w));
        rm = warpMaxF(rm);
        if (lane == 0) s_max[i * 16 + w] = rm;      // per-warp partial row max
    }
    if (lane == 0) s_cnt[w] = 0;
    __syncthreads();

    // ---- phase 2: warp w owns row w ----------------------------------------
    float* sc = s_sc + w * SS;
    float m;
    {
        float t = (lane < 16) ? s_max[w * 16 + lane] : -3.0e38f;
        m = warpMaxF(t);
    }

    // single pass: Z, S1 = sum p*(s-m), argmax-tie recording
    float z = 0.f, s1 = 0.f;
#pragma unroll 4
    for (int jj = 0; jj < 64; jj++) {
        int j = lane + (jj << 5);
        float s = sc[j];
        float x = s - m;
        float p = expf(x);
        z += p;
        s1 = fmaf(p, x, s1);
        if (s >= m) {   // tie with max (s <= m always)
            int pos = atomicAdd(&s_cnt[w], 1);
            if (pos < CAP) s_idx[w * CAP + pos] = (unsigned short)j;
        }
    }
    z  = warpSumF(z);
    s1 = warpSumF(s1);
    float hent = logf(z) - s1 / z;   // == -sum w log w (eps-free identity)
    __syncwarp();
    int cnt = s_cnt[w];

    int b = bh >> 3, hd = bh & 7;
    float* outp = &g_attn[((size_t)(b * SS + q0 + w)) * DD + hd * DH + lane * 2];

    if (hent >= 1.2f && cnt <= CAP) {
        // tk = 1 guaranteed (32*(1-H) < 1). kept set = argmax ties, p = 1 each.
        float wgt = 1.0f / ((float)cnt + EPSF * z);
        int d0 = lane * 2;
        float a0 = 0.f, a1 = 0.f;
        for (int t = 0; t < cnt; t++) {
            int j = s_idx[w * CAP + t];
            float2 vv = *(const float2*)(V + (size_t)j * DH + d0);
            a0 += vv.x; a1 += vv.y;
        }
        float2 o; o.x = a0 * wgt; o.y = a1 * wgt;
        *(float2*)outp = o;
    } else {
        // ---- exact general path (rare): reference-style entropy + topk ----
        float invZ = 1.0f / z;
        float he = 0.f;
        for (int jj = 0; jj < 64; jj++) {
            float p  = expf(sc[lane + (jj << 5)] - m);
            float ww = p * invZ;
            he -= ww * logf(ww + EPSF);
        }
        he = warpSumF(he);
        int tk = (int)(32.0f * (1.0f - he));
        tk = tk < 1 ? 1 : (tk > MAXK ? MAXK : tk);

        unsigned thr_u;
        if (tk == 1) {
            thr_u = ordf(m);
        } else {
            thr_u = 0xFFFFFFFFu;
            int removed = 0;
            while (removed < tk) {
                unsigned best = 0u;
                for (int jj = 0; jj < 64; jj++) {
                    unsigned u = ordf(sc[lane + (jj << 5)]);
                    if (u < thr_u && u > best) best = u;
                }
                best = warpMaxU(best);
                int c = 0;
                for (int jj = 0; jj < 64; jj++)
                    c += (ordf(sc[lane + (jj << 5)]) == best);
                c = warpSumI(c);
                removed += c;
                thr_u = best;
            }
        }

        if (lane == 0) s_cnt[w] = 0;
        __syncwarp();
        float P = 0.f;
        for (int jj = 0; jj < 64; jj++) {
            int j = lane + (jj << 5);
            float s = sc[j];
            if (ordf(s) >= thr_u) {
                P += expf(s - m);
                int pos = atomicAdd(&s_cnt[w], 1);
                if (pos < CAP) s_idx[w * CAP + pos] = (unsigned short)j;
            }
        }
        P = warpSumF(P);
        __syncwarp();
        int gcnt = s_cnt[w];
        float invDen = 1.0f / (P + EPSF * z);

        int d0 = lane * 2;
        float a0 = 0.f, a1 = 0.f;
        if (gcnt <= CAP) {
            for (int t = 0; t < gcnt; t++) {
                int j = s_idx[w * CAP + t];
                float p = expf(sc[j] - m);
                float2 vv = *(const float2*)(V + (size_t)j * DH + d0);
                a0 = fmaf(p, vv.x, a0);
                a1 = fmaf(p, vv.y, a1);
            }
        } else {
            for (int j = 0; j < SS; j++) {
                float s = sc[j];
                if (ordf(s) >= thr_u) {
                    float p = expf(s - m);
                    float2 vv = *(const float2*)(V + (size_t)j * DH + d0);
                    a0 = fmaf(p, vv.x, a0);
                    a1 = fmaf(p, vv.y, a1);
                }
            }
        }
        float2 o; o.x = a0 * invDen; o.y = a1 * invDen;
        *(float2*)outp = o;
    }
}

// ---------------- launch -----------------------------------------------------
extern "C" void kernel_launch(void* const* d_in, const int* in_sizes, int n_in,
                              void* d_out, int out_size)
{
    const float* x     = (const float*)d_in[0];
    const float* w_in  = (const float*)d_in[1];
    const float* b_in  = (const float*)d_in[2];
    const float* w_out = (const float*)d_in[3];
    const float* b_out = (const float*)d_in[4];
    float* out = (float*)d_out;

    float* pattn = nullptr;
    cudaGetSymbolAddress((void**)&pattn, g_attn);

    cudaFuncSetAttribute(attn_kernel,
                         cudaFuncAttributeMaxDynamicSharedMemorySize, ATTN_SMEM);

    // 1) QKV projection with head-layout scatter (768 blocks of 128x64)
    sgemm_nt<1><<<dim3((3*DD)/64, (BB*SS)/128), 256>>>(
        x, w_in, b_in, nullptr, BB*SS, 3*DD, DD);

    // 2) fused attention + entropy top-k
    attn_kernel<<<dim3(SS/TQ, BH), ATHREADS, ATTN_SMEM>>>();

    // 3) output projection (256 blocks of 128x64)
    sgemm_nt<0><<<dim3(DD/64, (BB*SS)/128), 256>>>(
        pattn, w_out, b_out, out, BB*SS, DD, DD);
}